// round 14
// baseline (speedup 1.0000x reference)
#include <cuda_runtime.h>
#include <cuda_fp16.h>
#include <mma.h>
#include <math.h>

using namespace nvcuda;

// ---------------- problem constants ----------------
#define L_SEQ   2048
#define D_MODEL 1024
#define D_INNER 2048
#define DT_RANK 64
#define NCHUNK  16
#define CHUNK   128

// ---------------- scratch (no allocations allowed) ----------------
__device__ float g_u0[L_SEQ * D_INNER];
__device__ float g_gate[L_SEQ * D_INNER];
__device__ float g_u[L_SEQ * D_INNER];
__device__ float g_t[L_SEQ * DT_RANK];
__device__ float g_delta[L_SEQ * D_INNER];

// split fp16 activations A' = [Ah | Al]  (M x 2K)
__device__ half g_xA[L_SEQ * 2 * D_MODEL];
__device__ half g_uA[L_SEQ * 2 * D_INNER];
__device__ half g_tA[L_SEQ * 2 * DT_RANK];
__device__ half g_yA[L_SEQ * 2 * D_INNER];

// fp16 weights B' = [Bh ; Bh]  (2K x ldb)  (hi duplicated)
__device__ half g_inB[2 * D_MODEL * D_INNER];
__device__ half g_gateB[2 * D_MODEL * D_INNER];
__device__ half g_dt1B[2 * D_INNER * 128];      // N padded 64 -> 128
__device__ half g_dt2B[2 * DT_RANK * D_INNER];
__device__ half g_outB[2 * D_INNER * D_MODEL];

// chunked scan state
__device__ float g_hS[NCHUNK * D_INNER * 16];
__device__ float g_pS[NCHUNK * D_INNER * 16];
__device__ float g_hin[NCHUNK * D_INNER * 16];

// ---------------- WMMA fp16 GEMM (double-buffered, fused epilogue) ----------
// C[M,N] = A'[M,Kp] @ B'[Kp,N] + bias (optional softplus), wmma-only.
// 128x128 CTA tile, 8 warps of 32x64, K chunk = 64.
// Dynamic smem: 2 stages of (As 128x72 + Bs 64x136) halves = 71680 B.
#define A_STAGE_H  (128 * 72)
#define B_STAGE_H  (64 * 136)
#define STAGE_H    (A_STAGE_H + B_STAGE_H)
#define WG_SMEM    (2 * STAGE_H * 2)   // bytes (71680); also >= 64KB f32 tile

__global__ __launch_bounds__(256, 1)
void wgemm(const half* __restrict__ A, const half* __restrict__ B,
           const float* __restrict__ bias, float* __restrict__ C,
           int Kp, int ldb, int ldc, int Nvalid, int softplus_ep)
{
    extern __shared__ half smem_h[];

    const int tid = threadIdx.x;
    const int wid = tid >> 5;
    const int m0 = blockIdx.y * 128;
    const int n0 = blockIdx.x * 128;
    const int warp_m = (wid & 3) * 32;
    const int warp_n = (wid >> 2) * 64;

    wmma::fragment<wmma::accumulator, 16, 16, 16, float> acc[2][4];
    #pragma unroll
    for (int mi = 0; mi < 2; mi++)
        #pragma unroll
        for (int nj = 0; nj < 4; nj++)
            wmma::fill_fragment(acc[mi][nj], 0.f);

    float4 pa[4], pb[4];

    auto gload = [&](int k0) {
        #pragma unroll
        for (int i = 0; i < 4; i++) {
            int idx = i * 256 + tid;
            int r = idx >> 3, c8 = (idx & 7) * 8;
            pa[i] = *(const float4*)(A + (size_t)(m0 + r) * Kp + k0 + c8);
        }
        #pragma unroll
        for (int i = 0; i < 4; i++) {
            int idx = i * 256 + tid;
            int r = idx >> 4, c8 = (idx & 15) * 8;
            pb[i] = *(const float4*)(B + (size_t)(k0 + r) * ldb + n0 + c8);
        }
    };
    auto sstore = [&](int s) {
        half* As = smem_h + (size_t)s * STAGE_H;
        half* Bs = As + A_STAGE_H;
        #pragma unroll
        for (int i = 0; i < 4; i++) {
            int idx = i * 256 + tid;
            int r = idx >> 3, c8 = (idx & 7) * 8;
            *(float4*)(As + r * 72 + c8) = pa[i];
        }
        #pragma unroll
        for (int i = 0; i < 4; i++) {
            int idx = i * 256 + tid;
            int r = idx >> 4, c8 = (idx & 15) * 8;
            *(float4*)(Bs + r * 136 + c8) = pb[i];
        }
    };

    const int nc = Kp >> 6;
    gload(0);
    sstore(0);
    __syncthreads();

    for (int c = 0; c < nc; c++) {
        if (c + 1 < nc) gload((c + 1) << 6);   // issue next-chunk loads early

        const half* As = smem_h + (size_t)(c & 1) * STAGE_H;
        const half* Bs = As + A_STAGE_H;
        #pragma unroll
        for (int kk = 0; kk < 4; kk++) {
            wmma::fragment<wmma::matrix_a, 16, 16, 16, half, wmma::row_major> fa[2];
            wmma::fragment<wmma::matrix_b, 16, 16, 16, half, wmma::row_major> fb[4];
            #pragma unroll
            for (int mi = 0; mi < 2; mi++)
                wmma::load_matrix_sync(fa[mi], As + (warp_m + mi * 16) * 72 + kk * 16, 72);
            #pragma unroll
            for (int nj = 0; nj < 4; nj++)
                wmma::load_matrix_sync(fb[nj], Bs + (kk * 16) * 136 + warp_n + nj * 16, 136);
            #pragma unroll
            for (int mi = 0; mi < 2; mi++)
                #pragma unroll
                for (int nj = 0; nj < 4; nj++)
                    wmma::mma_sync(acc[mi][nj], fa[mi], fb[nj], acc[mi][nj]);
        }
        if (c + 1 < nc) sstore((c + 1) & 1);   // waits on loads, fills other stage
        __syncthreads();
    }

    // fused epilogue: acc -> smem f32 tile (128x128) -> bias/softplus -> C
    float* ct = (float*)smem_h;
    #pragma unroll
    for (int mi = 0; mi < 2; mi++)
        #pragma unroll
        for (int nj = 0; nj < 4; nj++)
            wmma::store_matrix_sync(ct + (warp_m + mi * 16) * 128 + warp_n + nj * 16,
                                    acc[mi][nj], 128, wmma::mem_row_major);
    __syncthreads();

    #pragma unroll
    for (int i = 0; i < 16; i++) {
        int idx = i * 256 + tid;
        int r  = idx >> 5;
        int c4 = (idx & 31) * 4;
        int col = n0 + c4;
        if (col < Nvalid) {
            float4 v = *(float4*)(ct + r * 128 + c4);
            v.x += bias[col];     v.y += bias[col + 1];
            v.z += bias[col + 2]; v.w += bias[col + 3];
            if (softplus_ep) {
                v.x = (v.x > 20.f) ? v.x : log1pf(expf(v.x));
                v.y = (v.y > 20.f) ? v.y : log1pf(expf(v.y));
                v.z = (v.z > 20.f) ? v.z : log1pf(expf(v.z));
                v.w = (v.w > 20.f) ? v.w : log1pf(expf(v.w));
            }
            *(float4*)(C + (size_t)(m0 + r) * ldc + col) = v;
        }
    }
}

// ---------------- split kernels (intrinsics only) ----------------
__device__ __forceinline__ void split1(float v, half& h, half& l) {
    h = __float2half_rn(v);
    l = __float2half_rn(v - __half2float(h));
}

__global__ __launch_bounds__(256)
void split_act(const float4* __restrict__ V, half* __restrict__ O,
               int K4, int K, int total4)
{
    int i = blockIdx.x * 256 + threadIdx.x;
    if (i >= total4) return;
    int m = i / K4;
    int k = (i - m * K4) * 4;
    float4 v = V[i];
    half h0, l0, h1, l1, h2, l2, h3, l3;
    split1(v.x, h0, l0); split1(v.y, h1, l1);
    split1(v.z, h2, l2); split1(v.w, h3, l3);
    half2* p0 = (half2*)(O + (size_t)m * 2 * K + k);
    half2* p1 = (half2*)(O + (size_t)m * 2 * K + K + k);
    p0[0] = half2{h0, h1}; p0[1] = half2{h2, h3};
    p1[0] = half2{l0, l1}; p1[1] = half2{l2, l3};
}

__global__ __launch_bounds__(256)
void split_w(const float4* __restrict__ W, half* __restrict__ O,
             int N4, int N, int ldb, int K, int total4)
{
    int i = blockIdx.x * 256 + threadIdx.x;
    if (i >= total4) return;
    int k = i / N4;
    int n = (i - k * N4) * 4;
    float4 v = W[i];
    half2 h01 = {__float2half_rn(v.x), __float2half_rn(v.y)};
    half2 h23 = {__float2half_rn(v.z), __float2half_rn(v.w)};
    half2* p0 = (half2*)(O + (size_t)k * ldb + n);
    half2* p1 = (half2*)(O + (size_t)(K + k) * ldb + n);
    p0[0] = h01; p0[1] = h23;
    p1[0] = h01; p1[1] = h23;
}

__global__ __launch_bounds__(256)
void pad_dt1(half* __restrict__ O)
{
    int i = blockIdx.x * 256 + threadIdx.x;   // over 2*2048 * 32 half2 units
    int row = i >> 5;
    int c2  = (i & 31) * 2;
    ((half2*)(O + (size_t)row * 128 + 64 + c2))[0] = half2{(half)0.f, (half)0.f};
}

// ---------------- conv(width4) + SiLU + fp16 split (fused) ----------------
__global__ __launch_bounds__(256)
void conv_silu_split(const float* __restrict__ U0, const float* __restrict__ cw,
                     const float* __restrict__ cb, float* __restrict__ U,
                     half* __restrict__ UA)
{
    int idx = blockIdx.x * blockDim.x + threadIdx.x;
    if (idx >= L_SEQ * D_INNER) return;
    int d = idx & (D_INNER - 1);
    int l = idx >> 11;
    float w0 = cw[d * 4 + 0], w1 = cw[d * 4 + 1], w2 = cw[d * 4 + 2], w3 = cw[d * 4 + 3];
    float acc = cb[d] + w3 * U0[idx];
    if (l >= 1) acc = fmaf(w2, U0[idx - D_INNER], acc);
    if (l >= 2) acc = fmaf(w1, U0[idx - 2 * D_INNER], acc);
    if (l >= 3) acc = fmaf(w0, U0[idx - 3 * D_INNER], acc);
    float s = acc / (1.f + expf(-acc));
    U[idx] = s;
    half h, lo;
    split1(s, h, lo);
    size_t base = (size_t)l * 2 * D_INNER + d;
    UA[base] = h;
    UA[base + D_INNER] = lo;
}

// ---------------- chunked 2-pass SSM scan ----------------
__global__ __launch_bounds__(256)
void scan_pass1(const float* __restrict__ delta, const float* __restrict__ u,
                const float* __restrict__ A_log, const float* __restrict__ Bm,
                float* __restrict__ hS, float* __restrict__ pS)
{
    const int tid  = threadIdx.x;
    const int n    = tid & 15;
    const int dgrp = tid >> 4;
    const int bx   = blockIdx.x;
    const int d     = (bx & 127) * 16 + dgrp;
    const int chunk = bx >> 7;

    const float A  = -expf(A_log[n]);
    const float Bn = Bm[n * D_INNER + d];
    const bool  smallA = fabsf(A) < 1e-6f;
    const float invA   = smallA ? 0.f : 1.f / A;

    float h = 0.f, p = 1.f;
    size_t idx = (size_t)(chunk * CHUNK) * D_INNER + d;
    for (int l = 0; l < CHUNK; l++) {
        float dt = delta[idx];
        float uu = u[idx];
        float dA = dt * A;
        float ab = __expf(dA);
        float ex = smallA ? dt * (1.f + 0.5f * dA) : (ab - 1.f) * invA;
        h = fmaf(ab, h, ex * Bn * uu);
        p *= ab;
        idx += D_INNER;
    }
    int o = (chunk * D_INNER + d) * 16 + n;
    hS[o] = h;
    pS[o] = p;
}

__global__ __launch_bounds__(256)
void scan_mid(const float* __restrict__ hS, const float* __restrict__ pS,
              float* __restrict__ hin)
{
    int i = blockIdx.x * 256 + threadIdx.x;
    int d = i >> 4, n = i & 15;
    float carry = 0.f;
    #pragma unroll
    for (int c = 0; c < NCHUNK; c++) {
        int o = (c * D_INNER + d) * 16 + n;
        hin[o] = carry;
        carry = fmaf(pS[o], carry, hS[o]);
    }
}

__global__ __launch_bounds__(256)
void scan_pass2(const float* __restrict__ delta, const float* __restrict__ u,
                const float* __restrict__ gpre, const float* __restrict__ A_log,
                const float* __restrict__ Bm, const float* __restrict__ Cm,
                const float* __restrict__ Dv, const float* __restrict__ hin,
                half* __restrict__ YA)
{
    const int tid  = threadIdx.x;
    const int n    = tid & 15;
    const int dgrp = tid >> 4;
    const int bx   = blockIdx.x;
    const int d     = (bx & 127) * 16 + dgrp;
    const int chunk = bx >> 7;

    const float A  = -expf(A_log[n]);
    const float Bn = Bm[n * D_INNER + d];
    const float Cn = Cm[n * D_INNER + d];
    const float Dd = Dv[d];
    const bool  smallA = fabsf(A) < 1e-6f;
    const float invA   = smallA ? 0.f : 1.f / A;

    float h = hin[(chunk * D_INNER + d) * 16 + n];
    size_t idx = (size_t)(chunk * CHUNK) * D_INNER + d;
    size_t ybase = (size_t)(chunk * CHUNK) * 2 * D_INNER + d;
    for (int l = 0; l < CHUNK; l++) {
        float dt = delta[idx];
        float uu = u[idx];
        float dA = dt * A;
        float ab = __expf(dA);
        float ex = smallA ? dt * (1.f + 0.5f * dA) : (ab - 1.f) * invA;
        h = fmaf(ab, h, ex * Bn * uu);
        float c = h * Cn;
        c += __shfl_xor_sync(0xffffffffu, c, 1);
        c += __shfl_xor_sync(0xffffffffu, c, 2);
        c += __shfl_xor_sync(0xffffffffu, c, 4);
        c += __shfl_xor_sync(0xffffffffu, c, 8);
        if (n == 0) {
            float gg = gpre[idx];
            float sil = gg / (1.f + expf(-gg));
            float val = (c + Dd * uu) * sil;
            half hh, ll;
            split1(val, hh, ll);
            YA[ybase] = hh;
            YA[ybase + D_INNER] = ll;
        }
        idx += D_INNER;
        ybase += 2 * D_INNER;
    }
}

// ---------------- launcher ----------------
extern "C" void kernel_launch(void* const* d_in, const int* in_sizes, int n_in,
                              void* d_out, int out_size)
{
    const float* x      = (const float*)d_in[0];
    const float* in_w   = (const float*)d_in[1];
    const float* in_b   = (const float*)d_in[2];
    const float* conv_w = (const float*)d_in[3];
    const float* conv_b = (const float*)d_in[4];
    const float* A_log  = (const float*)d_in[5];
    const float* B_mat  = (const float*)d_in[6];
    const float* C_mat  = (const float*)d_in[7];
    const float* D_vec  = (const float*)d_in[8];
    const float* gate_w = (const float*)d_in[9];
    const float* gate_b = (const float*)d_in[10];
    const float* dt1_w  = (const float*)d_in[11];
    const float* dt1_b  = (const float*)d_in[12];
    const float* dt2_w  = (const float*)d_in[13];
    const float* dt2_b  = (const float*)d_in[14];
    const float* out_w  = (const float*)d_in[15];
    const float* out_b  = (const float*)d_in[16];
    float* out = (float*)d_out;

    float *u0, *gate, *u, *t, *delta, *hS, *pS, *hin;
    half *xA, *uA, *tA, *yA, *inB, *gateB, *dt1B, *dt2B, *outB;
    cudaGetSymbolAddress((void**)&u0, g_u0);       cudaGetSymbolAddress((void**)&gate, g_gate);
    cudaGetSymbolAddress((void**)&u, g_u);         cudaGetSymbolAddress((void**)&t, g_t);
    cudaGetSymbolAddress((void**)&delta, g_delta);
    cudaGetSymbolAddress((void**)&hS, g_hS);       cudaGetSymbolAddress((void**)&pS, g_pS);
    cudaGetSymbolAddress((void**)&hin, g_hin);
    cudaGetSymbolAddress((void**)&xA, g_xA);       cudaGetSymbolAddress((void**)&uA, g_uA);
    cudaGetSymbolAddress((void**)&tA, g_tA);       cudaGetSymbolAddress((void**)&yA, g_yA);
    cudaGetSymbolAddress((void**)&inB, g_inB);     cudaGetSymbolAddress((void**)&gateB, g_gateB);
    cudaGetSymbolAddress((void**)&dt1B, g_dt1B);   cudaGetSymbolAddress((void**)&dt2B, g_dt2B);
    cudaGetSymbolAddress((void**)&outB, g_outB);

    cudaFuncSetAttribute(wgemm, cudaFuncAttributeMaxDynamicSharedMemorySize, WG_SMEM);

    // ---- weight splits (W[K,N] -> [2K,ldb], hi duplicated) ----
    split_w<<<(D_MODEL * D_INNER / 4 + 255) / 256, 256>>>((const float4*)in_w,   inB,
        D_INNER / 4, D_INNER, D_INNER, D_MODEL, D_MODEL * D_INNER / 4);
    split_w<<<(D_MODEL * D_INNER / 4 + 255) / 256, 256>>>((const float4*)gate_w, gateB,
        D_INNER / 4, D_INNER, D_INNER, D_MODEL, D_MODEL * D_INNER / 4);
    split_w<<<(D_INNER * DT_RANK / 4 + 255) / 256, 256>>>((const float4*)dt1_w,  dt1B,
        DT_RANK / 4, DT_RANK, 128, D_INNER, D_INNER * DT_RANK / 4);
    pad_dt1<<<(2 * D_INNER * 32 + 255) / 256, 256>>>(dt1B);
    split_w<<<(DT_RANK * D_INNER / 4 + 255) / 256, 256>>>((const float4*)dt2_w,  dt2B,
        D_INNER / 4, D_INNER, D_INNER, DT_RANK, DT_RANK * D_INNER / 4);
    split_w<<<(D_INNER * D_MODEL / 4 + 255) / 256, 256>>>((const float4*)out_w,  outB,
        D_MODEL / 4, D_MODEL, D_MODEL, D_INNER, D_INNER * D_MODEL / 4);

    // ---- x split ----
    split_act<<<(L_SEQ * D_MODEL / 4 + 255) / 256, 256>>>((const float4*)x, xA,
        D_MODEL / 4, D_MODEL, L_SEQ * D_MODEL / 4);

    // ---- in-proj + gate-proj ----
    wgemm<<<dim3(D_INNER / 128, L_SEQ / 128), 256, WG_SMEM>>>(
        xA, inB, in_b, u0, 2 * D_MODEL, D_INNER, D_INNER, D_INNER, 0);
    wgemm<<<dim3(D_INNER / 128, L_SEQ / 128), 256, WG_SMEM>>>(
        xA, gateB, gate_b, gate, 2 * D_MODEL, D_INNER, D_INNER, D_INNER, 0);

    // ---- conv + silu + split (fused) ----
    conv_silu_split<<<(L_SEQ * D_INNER) / 256, 256>>>(u0, conv_w, conv_b, u, uA);

    // ---- dt1 (N padded to 128, valid 64, compact ldc=64) ----
    wgemm<<<dim3(1, L_SEQ / 128), 256, WG_SMEM>>>(
        uA, dt1B, dt1_b, t, 2 * D_INNER, 128, DT_RANK, DT_RANK, 0);

    // ---- t split + dt2 (+softplus) ----
    split_act<<<(L_SEQ * DT_RANK / 4 + 255) / 256, 256>>>((const float4*)t, tA,
        DT_RANK / 4, DT_RANK, L_SEQ * DT_RANK / 4);
    wgemm<<<dim3(D_INNER / 128, L_SEQ / 128), 256, WG_SMEM>>>(
        tA, dt2B, dt2_b, delta, 2 * DT_RANK, D_INNER, D_INNER, D_INNER, 1);

    // ---- chunked scan (pass2 emits fp16 split y directly) ----
    scan_pass1<<<NCHUNK * (D_INNER / 16), 256>>>(delta, u, A_log, B_mat, hS, pS);
    scan_mid<<<(D_INNER * 16) / 256, 256>>>(hS, pS, hin);
    scan_pass2<<<NCHUNK * (D_INNER / 16), 256>>>(delta, u, gate, A_log, B_mat,
                                                 C_mat, D_vec, hin, yA);

    // ---- out-proj ----
    wgemm<<<dim3(D_MODEL / 128, L_SEQ / 128), 256, WG_SMEM>>>(
        yA, outB, out_b, out, 2 * D_INNER, D_MODEL, D_MODEL, D_MODEL, 0);
}

// round 15
// speedup vs baseline: 1.7175x; 1.7175x over previous
#include <cuda_runtime.h>
#include <cuda_fp16.h>
#include <mma.h>
#include <math.h>

using namespace nvcuda;

// ---------------- problem constants ----------------
#define L_SEQ   2048
#define D_MODEL 1024
#define D_INNER 2048
#define DT_RANK 64
#define NCHUNK  16
#define CHUNK   128
#define SPLITK  8

// ---------------- scratch (no allocations allowed) ----------------
__device__ float g_u0[L_SEQ * D_INNER];
__device__ float g_gate[L_SEQ * D_INNER];
__device__ float g_u[L_SEQ * D_INNER];
__device__ float g_t[L_SEQ * DT_RANK];
__device__ float g_tpart[SPLITK * L_SEQ * DT_RANK];
__device__ float g_delta[L_SEQ * D_INNER];

// split fp16 activations A' = [Ah | Al]  (M x 2K)
__device__ half g_xA[L_SEQ * 2 * D_MODEL];
__device__ half g_uA[L_SEQ * 2 * D_INNER];
__device__ half g_tA[L_SEQ * 2 * DT_RANK];
__device__ half g_yA[L_SEQ * 2 * D_INNER];

// fp16 weights B' = [Bh ; Bh]  (2K x ldb)  (hi duplicated)
__device__ half g_inB[2 * D_MODEL * D_INNER];
__device__ half g_gateB[2 * D_MODEL * D_INNER];
__device__ half g_dt1B[2 * D_INNER * 128];      // N padded 64 -> 128
__device__ half g_dt2B[2 * DT_RANK * D_INNER];
__device__ half g_outB[2 * D_INNER * D_MODEL];

// chunked scan state
__device__ float g_hS[NCHUNK * D_INNER * 16];
__device__ float g_pS[NCHUNK * D_INNER * 16];
__device__ float g_hin[NCHUNK * D_INNER * 16];

// ---------------- WMMA fp16 GEMM (R13 mainloop + fused per-warp epilogue) ---
// C[M,N] = A'[M,Kp] @ B'[Kp,N] (+ bias / softplus unless split-K raw mode).
// 128x128 CTA tile, 8 warps of 32x64, K chunk = 64, static smem.
// gridDim.z > 1 => split-K: slice z covers K range [z*Kp, (z+1)*Kp) of A (row
// stride lda) and B; writes RAW partials to C + z*(gridDim.y*128)*ldc.
__global__ __launch_bounds__(256, 1)
void wgemm(const half* __restrict__ A, const half* __restrict__ B,
           const float* __restrict__ bias, float* __restrict__ C,
           int Kp, int lda, int ldb, int ldc, int Nvalid, int softplus_ep)
{
    __shared__ half As[128][72];    // 64 cols + 8 pad
    __shared__ half Bs[64][136];    // 128 cols + 8 pad
    __shared__ float esc[8][256];   // per-warp 16x16 f32 epilogue scratch

    const int tid = threadIdx.x;
    const int wid = tid >> 5;
    const int lane = tid & 31;
    const int m0 = blockIdx.y * 128;
    const int n0 = blockIdx.x * 128;
    const int warp_m = (wid & 3) * 32;
    const int warp_n = (wid >> 2) * 64;

    // split-K slice offsets
    const bool raw = (gridDim.z > 1);
    A += (size_t)blockIdx.z * Kp;            // column offset within row (stride lda)
    B += (size_t)blockIdx.z * Kp * ldb;
    if (raw) C += (size_t)blockIdx.z * gridDim.y * 128 * ldc;

    wmma::fragment<wmma::accumulator, 16, 16, 16, float> acc[2][4];
    #pragma unroll
    for (int mi = 0; mi < 2; mi++)
        #pragma unroll
        for (int nj = 0; nj < 4; nj++)
            wmma::fill_fragment(acc[mi][nj], 0.f);

    float4 pa[4], pb[4];

    auto gload = [&](int k0) {
        #pragma unroll
        for (int i = 0; i < 4; i++) {
            int idx = i * 256 + tid;
            int r = idx >> 3, c8 = (idx & 7) * 8;
            pa[i] = *(const float4*)(A + (size_t)(m0 + r) * lda + k0 + c8);
        }
        #pragma unroll
        for (int i = 0; i < 4; i++) {
            int idx = i * 256 + tid;
            int r = idx >> 4, c8 = (idx & 15) * 8;
            pb[i] = *(const float4*)(B + (size_t)(k0 + r) * ldb + n0 + c8);
        }
    };
    auto sstore = [&]() {
        #pragma unroll
        for (int i = 0; i < 4; i++) {
            int idx = i * 256 + tid;
            int r = idx >> 3, c8 = (idx & 7) * 8;
            *(float4*)&As[r][c8] = pa[i];
        }
        #pragma unroll
        for (int i = 0; i < 4; i++) {
            int idx = i * 256 + tid;
            int r = idx >> 4, c8 = (idx & 15) * 8;
            *(float4*)&Bs[r][c8] = pb[i];
        }
    };

    gload(0);
    sstore();
    __syncthreads();

    for (int k0 = 0; k0 < Kp; k0 += 64) {
        if (k0 + 64 < Kp) gload(k0 + 64);   // prefetch next tile into regs

        #pragma unroll
        for (int kk = 0; kk < 4; kk++) {
            wmma::fragment<wmma::matrix_a, 16, 16, 16, half, wmma::row_major> fa[2];
            wmma::fragment<wmma::matrix_b, 16, 16, 16, half, wmma::row_major> fb[4];
            #pragma unroll
            for (int mi = 0; mi < 2; mi++)
                wmma::load_matrix_sync(fa[mi], &As[warp_m + mi * 16][kk * 16], 72);
            #pragma unroll
            for (int nj = 0; nj < 4; nj++)
                wmma::load_matrix_sync(fb[nj], &Bs[kk * 16][warp_n + nj * 16], 136);
            #pragma unroll
            for (int mi = 0; mi < 2; mi++)
                #pragma unroll
                for (int nj = 0; nj < 4; nj++)
                    wmma::mma_sync(acc[mi][nj], fa[mi], fb[nj], acc[mi][nj]);
        }
        __syncthreads();
        if (k0 + 64 < Kp) {
            sstore();
            __syncthreads();
        }
    }

    // fused epilogue: per-warp fragment roundtrip through esc (no block sync)
    #pragma unroll
    for (int mi = 0; mi < 2; mi++) {
        #pragma unroll
        for (int nj = 0; nj < 4; nj++) {
            int colf = n0 + warp_n + nj * 16;
            if (colf >= Nvalid) continue;            // fragment fully out of range
            wmma::store_matrix_sync(esc[wid], acc[mi][nj], 16, wmma::mem_row_major);
            __syncwarp();
            int r   = lane >> 1;                     // 0..15
            int cb  = (lane & 1) * 8;                // 0 or 8
            int row = m0 + warp_m + mi * 16 + r;
            int col = colf + cb;
            float4 v0 = *(float4*)&esc[wid][r * 16 + cb];
            float4 v1 = *(float4*)&esc[wid][r * 16 + cb + 4];
            if (!raw) {
                v0.x += bias[col];     v0.y += bias[col + 1];
                v0.z += bias[col + 2]; v0.w += bias[col + 3];
                v1.x += bias[col + 4]; v1.y += bias[col + 5];
                v1.z += bias[col + 6]; v1.w += bias[col + 7];
                if (softplus_ep) {
                    v0.x = (v0.x > 20.f) ? v0.x : log1pf(expf(v0.x));
                    v0.y = (v0.y > 20.f) ? v0.y : log1pf(expf(v0.y));
                    v0.z = (v0.z > 20.f) ? v0.z : log1pf(expf(v0.z));
                    v0.w = (v0.w > 20.f) ? v0.w : log1pf(expf(v0.w));
                    v1.x = (v1.x > 20.f) ? v1.x : log1pf(expf(v1.x));
                    v1.y = (v1.y > 20.f) ? v1.y : log1pf(expf(v1.y));
                    v1.z = (v1.z > 20.f) ? v1.z : log1pf(expf(v1.z));
                    v1.w = (v1.w > 20.f) ? v1.w : log1pf(expf(v1.w));
                }
            }
            *(float4*)(C + (size_t)row * ldc + col)     = v0;
            *(float4*)(C + (size_t)row * ldc + col + 4) = v1;
            __syncwarp();
        }
    }
}

// reduce split-K partials for t: t[i] = bias[i%64] + sum_z part[z][i]
__global__ __launch_bounds__(256)
void reduce_t(const float* __restrict__ part, const float* __restrict__ bias,
              float* __restrict__ T)
{
    int i = blockIdx.x * 256 + threadIdx.x;   // over 2048*64
    float s = bias[i & 63];
    #pragma unroll
    for (int z = 0; z < SPLITK; z++)
        s += part[(size_t)z * (L_SEQ * DT_RANK) + i];
    T[i] = s;
}

// ---------------- split kernels (intrinsics only) ----------------
__device__ __forceinline__ void split1(float v, half& h, half& l) {
    h = __float2half_rn(v);
    l = __float2half_rn(v - __half2float(h));
}

__global__ __launch_bounds__(256)
void split_act(const float4* __restrict__ V, half* __restrict__ O,
               int K4, int K, int total4)
{
    int i = blockIdx.x * 256 + threadIdx.x;
    if (i >= total4) return;
    int m = i / K4;
    int k = (i - m * K4) * 4;
    float4 v = V[i];
    half h0, l0, h1, l1, h2, l2, h3, l3;
    split1(v.x, h0, l0); split1(v.y, h1, l1);
    split1(v.z, h2, l2); split1(v.w, h3, l3);
    half2* p0 = (half2*)(O + (size_t)m * 2 * K + k);
    half2* p1 = (half2*)(O + (size_t)m * 2 * K + K + k);
    p0[0] = half2{h0, h1}; p0[1] = half2{h2, h3};
    p1[0] = half2{l0, l1}; p1[1] = half2{l2, l3};
}

__global__ __launch_bounds__(256)
void split_w(const float4* __restrict__ W, half* __restrict__ O,
             int N4, int N, int ldb, int K, int total4)
{
    int i = blockIdx.x * 256 + threadIdx.x;
    if (i >= total4) return;
    int k = i / N4;
    int n = (i - k * N4) * 4;
    float4 v = W[i];
    half2 h01 = {__float2half_rn(v.x), __float2half_rn(v.y)};
    half2 h23 = {__float2half_rn(v.z), __float2half_rn(v.w)};
    half2* p0 = (half2*)(O + (size_t)k * ldb + n);
    half2* p1 = (half2*)(O + (size_t)(K + k) * ldb + n);
    p0[0] = h01; p0[1] = h23;
    p1[0] = h01; p1[1] = h23;
}

__global__ __launch_bounds__(256)
void pad_dt1(half* __restrict__ O)
{
    int i = blockIdx.x * 256 + threadIdx.x;   // over 2*2048 * 32 half2 units
    int row = i >> 5;
    int c2  = (i & 31) * 2;
    ((half2*)(O + (size_t)row * 128 + 64 + c2))[0] = half2{(half)0.f, (half)0.f};
}

// ---------------- conv(width4) + SiLU + fp16 split (fused) ----------------
__global__ __launch_bounds__(256)
void conv_silu_split(const float* __restrict__ U0, const float* __restrict__ cw,
                     const float* __restrict__ cb, float* __restrict__ U,
                     half* __restrict__ UA)
{
    int idx = blockIdx.x * blockDim.x + threadIdx.x;
    if (idx >= L_SEQ * D_INNER) return;
    int d = idx & (D_INNER - 1);
    int l = idx >> 11;
    float w0 = cw[d * 4 + 0], w1 = cw[d * 4 + 1], w2 = cw[d * 4 + 2], w3 = cw[d * 4 + 3];
    float acc = cb[d] + w3 * U0[idx];
    if (l >= 1) acc = fmaf(w2, U0[idx - D_INNER], acc);
    if (l >= 2) acc = fmaf(w1, U0[idx - 2 * D_INNER], acc);
    if (l >= 3) acc = fmaf(w0, U0[idx - 3 * D_INNER], acc);
    float s = acc / (1.f + expf(-acc));
    U[idx] = s;
    half h, lo;
    split1(s, h, lo);
    size_t base = (size_t)l * 2 * D_INNER + d;
    UA[base] = h;
    UA[base + D_INNER] = lo;
}

// ---------------- chunked 2-pass SSM scan ----------------
__global__ __launch_bounds__(256)
void scan_pass1(const float* __restrict__ delta, const float* __restrict__ u,
                const float* __restrict__ A_log, const float* __restrict__ Bm,
                float* __restrict__ hS, float* __restrict__ pS)
{
    const int tid  = threadIdx.x;
    const int n    = tid & 15;
    const int dgrp = tid >> 4;
    const int bx   = blockIdx.x;
    const int d     = (bx & 127) * 16 + dgrp;
    const int chunk = bx >> 7;

    const float A  = -expf(A_log[n]);
    const float Bn = Bm[n * D_INNER + d];
    const bool  smallA = fabsf(A) < 1e-6f;
    const float invA   = smallA ? 0.f : 1.f / A;

    float h = 0.f, p = 1.f;
    size_t idx = (size_t)(chunk * CHUNK) * D_INNER + d;
    for (int l = 0; l < CHUNK; l++) {
        float dt = delta[idx];
        float uu = u[idx];
        float dA = dt * A;
        float ab = __expf(dA);
        float ex = smallA ? dt * (1.f + 0.5f * dA) : (ab - 1.f) * invA;
        h = fmaf(ab, h, ex * Bn * uu);
        p *= ab;
        idx += D_INNER;
    }
    int o = (chunk * D_INNER + d) * 16 + n;
    hS[o] = h;
    pS[o] = p;
}

__global__ __launch_bounds__(256)
void scan_mid(const float* __restrict__ hS, const float* __restrict__ pS,
              float* __restrict__ hin)
{
    int i = blockIdx.x * 256 + threadIdx.x;
    int d = i >> 4, n = i & 15;
    float carry = 0.f;
    #pragma unroll
    for (int c = 0; c < NCHUNK; c++) {
        int o = (c * D_INNER + d) * 16 + n;
        hin[o] = carry;
        carry = fmaf(pS[o], carry, hS[o]);
    }
}

__global__ __launch_bounds__(256)
void scan_pass2(const float* __restrict__ delta, const float* __restrict__ u,
                const float* __restrict__ gpre, const float* __restrict__ A_log,
                const float* __restrict__ Bm, const float* __restrict__ Cm,
                const float* __restrict__ Dv, const float* __restrict__ hin,
                half* __restrict__ YA)
{
    const int tid  = threadIdx.x;
    const int n    = tid & 15;
    const int dgrp = tid >> 4;
    const int bx   = blockIdx.x;
    const int d     = (bx & 127) * 16 + dgrp;
    const int chunk = bx >> 7;

    const float A  = -expf(A_log[n]);
    const float Bn = Bm[n * D_INNER + d];
    const float Cn = Cm[n * D_INNER + d];
    const float Dd = Dv[d];
    const bool  smallA = fabsf(A) < 1e-6f;
    const float invA   = smallA ? 0.f : 1.f / A;

    float h = hin[(chunk * D_INNER + d) * 16 + n];
    size_t idx = (size_t)(chunk * CHUNK) * D_INNER + d;
    size_t ybase = (size_t)(chunk * CHUNK) * 2 * D_INNER + d;
    for (int l = 0; l < CHUNK; l++) {
        float dt = delta[idx];
        float uu = u[idx];
        float dA = dt * A;
        float ab = __expf(dA);
        float ex = smallA ? dt * (1.f + 0.5f * dA) : (ab - 1.f) * invA;
        h = fmaf(ab, h, ex * Bn * uu);
        float c = h * Cn;
        c += __shfl_xor_sync(0xffffffffu, c, 1);
        c += __shfl_xor_sync(0xffffffffu, c, 2);
        c += __shfl_xor_sync(0xffffffffu, c, 4);
        c += __shfl_xor_sync(0xffffffffu, c, 8);
        if (n == 0) {
            float gg = gpre[idx];
            float sil = gg / (1.f + expf(-gg));
            float val = (c + Dd * uu) * sil;
            half hh, ll;
            split1(val, hh, ll);
            YA[ybase] = hh;
            YA[ybase + D_INNER] = ll;
        }
        idx += D_INNER;
        ybase += 2 * D_INNER;
    }
}

// ---------------- launcher ----------------
extern "C" void kernel_launch(void* const* d_in, const int* in_sizes, int n_in,
                              void* d_out, int out_size)
{
    const float* x      = (const float*)d_in[0];
    const float* in_w   = (const float*)d_in[1];
    const float* in_b   = (const float*)d_in[2];
    const float* conv_w = (const float*)d_in[3];
    const float* conv_b = (const float*)d_in[4];
    const float* A_log  = (const float*)d_in[5];
    const float* B_mat  = (const float*)d_in[6];
    const float* C_mat  = (const float*)d_in[7];
    const float* D_vec  = (const float*)d_in[8];
    const float* gate_w = (const float*)d_in[9];
    const float* gate_b = (const float*)d_in[10];
    const float* dt1_w  = (const float*)d_in[11];
    const float* dt1_b  = (const float*)d_in[12];
    const float* dt2_w  = (const float*)d_in[13];
    const float* dt2_b  = (const float*)d_in[14];
    const float* out_w  = (const float*)d_in[15];
    const float* out_b  = (const float*)d_in[16];
    float* out = (float*)d_out;

    float *u0, *gate, *u, *t, *tpart, *delta, *hS, *pS, *hin;
    half *xA, *uA, *tA, *yA, *inB, *gateB, *dt1B, *dt2B, *outB;
    cudaGetSymbolAddress((void**)&u0, g_u0);       cudaGetSymbolAddress((void**)&gate, g_gate);
    cudaGetSymbolAddress((void**)&u, g_u);         cudaGetSymbolAddress((void**)&t, g_t);
    cudaGetSymbolAddress((void**)&tpart, g_tpart); cudaGetSymbolAddress((void**)&delta, g_delta);
    cudaGetSymbolAddress((void**)&hS, g_hS);       cudaGetSymbolAddress((void**)&pS, g_pS);
    cudaGetSymbolAddress((void**)&hin, g_hin);
    cudaGetSymbolAddress((void**)&xA, g_xA);       cudaGetSymbolAddress((void**)&uA, g_uA);
    cudaGetSymbolAddress((void**)&tA, g_tA);       cudaGetSymbolAddress((void**)&yA, g_yA);
    cudaGetSymbolAddress((void**)&inB, g_inB);     cudaGetSymbolAddress((void**)&gateB, g_gateB);
    cudaGetSymbolAddress((void**)&dt1B, g_dt1B);   cudaGetSymbolAddress((void**)&dt2B, g_dt2B);
    cudaGetSymbolAddress((void**)&outB, g_outB);

    // ---- weight splits (W[K,N] -> [2K,ldb], hi duplicated) ----
    split_w<<<(D_MODEL * D_INNER / 4 + 255) / 256, 256>>>((const float4*)in_w,   inB,
        D_INNER / 4, D_INNER, D_INNER, D_MODEL, D_MODEL * D_INNER / 4);
    split_w<<<(D_MODEL * D_INNER / 4 + 255) / 256, 256>>>((const float4*)gate_w, gateB,
        D_INNER / 4, D_INNER, D_INNER, D_MODEL, D_MODEL * D_INNER / 4);
    split_w<<<(D_INNER * DT_RANK / 4 + 255) / 256, 256>>>((const float4*)dt1_w,  dt1B,
        DT_RANK / 4, DT_RANK, 128, D_INNER, D_INNER * DT_RANK / 4);
    pad_dt1<<<(2 * D_INNER * 32 + 255) / 256, 256>>>(dt1B);
    split_w<<<(DT_RANK * D_INNER / 4 + 255) / 256, 256>>>((const float4*)dt2_w,  dt2B,
        D_INNER / 4, D_INNER, D_INNER, DT_RANK, DT_RANK * D_INNER / 4);
    split_w<<<(D_INNER * D_MODEL / 4 + 255) / 256, 256>>>((const float4*)out_w,  outB,
        D_MODEL / 4, D_MODEL, D_MODEL, D_INNER, D_INNER * D_MODEL / 4);

    // ---- x split ----
    split_act<<<(L_SEQ * D_MODEL / 4 + 255) / 256, 256>>>((const float4*)x, xA,
        D_MODEL / 4, D_MODEL, L_SEQ * D_MODEL / 4);

    // ---- in-proj + gate-proj ----
    wgemm<<<dim3(D_INNER / 128, L_SEQ / 128, 1), 256>>>(
        xA, inB, in_b, u0, 2 * D_MODEL, 2 * D_MODEL, D_INNER, D_INNER, D_INNER, 0);
    wgemm<<<dim3(D_INNER / 128, L_SEQ / 128, 1), 256>>>(
        xA, gateB, gate_b, gate, 2 * D_MODEL, 2 * D_MODEL, D_INNER, D_INNER, D_INNER, 0);

    // ---- conv + silu + split (fused) ----
    conv_silu_split<<<(L_SEQ * D_INNER) / 256, 256>>>(u0, conv_w, conv_b, u, uA);

    // ---- dt1: split-K=8 raw partials (grid 1x16x8 = 128 CTAs) + reduce ----
    wgemm<<<dim3(1, L_SEQ / 128, SPLITK), 256>>>(
        uA, dt1B, dt1_b, tpart, (2 * D_INNER) / SPLITK, 2 * D_INNER, 128, DT_RANK,
        DT_RANK, 0);
    reduce_t<<<(L_SEQ * DT_RANK) / 256, 256>>>(tpart, dt1_b, t);

    // ---- t split + dt2 (+softplus) ----
    split_act<<<(L_SEQ * DT_RANK / 4 + 255) / 256, 256>>>((const float4*)t, tA,
        DT_RANK / 4, DT_RANK, L_SEQ * DT_RANK / 4);
    wgemm<<<dim3(D_INNER / 128, L_SEQ / 128, 1), 256>>>(
        tA, dt2B, dt2_b, delta, 2 * DT_RANK, 2 * DT_RANK, D_INNER, D_INNER, D_INNER, 1);

    // ---- chunked scan (pass2 emits fp16 split y directly) ----
    scan_pass1<<<NCHUNK * (D_INNER / 16), 256>>>(delta, u, A_log, B_mat, hS, pS);
    scan_mid<<<(D_INNER * 16) / 256, 256>>>(hS, pS, hin);
    scan_pass2<<<NCHUNK * (D_INNER / 16), 256>>>(delta, u, gate, A_log, B_mat,
                                                 C_mat, D_vec, hin, yA);

    // ---- out-proj ----
    wgemm<<<dim3(D_MODEL / 128, L_SEQ / 128, 1), 256>>>(
        yA, outB, out_b, out, 2 * D_INNER, 2 * D_INNER, D_MODEL, D_MODEL, D_MODEL, 0);
}

// round 16
// speedup vs baseline: 1.7623x; 1.0261x over previous
#include <cuda_runtime.h>
#include <cuda_fp16.h>
#include <mma.h>
#include <math.h>

using namespace nvcuda;

// ---------------- problem constants ----------------
#define L_SEQ   2048
#define D_MODEL 1024
#define D_INNER 2048
#define DT_RANK 64
#define NCHUNK  16
#define CHUNK   128
#define SPLITK  8

// ---------------- scratch (no allocations allowed) ----------------
__device__ float g_ug[L_SEQ * 2 * D_INNER];     // [u0 | gate] combined, ld 4096
__device__ float g_u[L_SEQ * D_INNER];
__device__ float g_t[L_SEQ * DT_RANK];
__device__ float g_tpart[SPLITK * L_SEQ * DT_RANK];
__device__ float g_delta[L_SEQ * D_INNER];

// split fp16 activations A' = [Ah | Al]  (M x 2K)
__device__ half g_xA[L_SEQ * 2 * D_MODEL];
__device__ half g_uA[L_SEQ * 2 * D_INNER];
__device__ half g_tA[L_SEQ * 2 * DT_RANK];
__device__ half g_yA[L_SEQ * 2 * D_INNER];

// fp16 weights B' = [Bh ; Bh]  (2K x ldb)
__device__ half g_ugB[2 * D_MODEL * 2 * D_INNER];   // [in | gate] fused, ldb 4096
__device__ half g_dt1B[2 * D_INNER * 128];          // N padded 64 -> 128
__device__ half g_dt2B[2 * DT_RANK * D_INNER];
__device__ half g_outB[2 * D_INNER * D_MODEL];

// chunked scan state
__device__ float g_hS[NCHUNK * D_INNER * 16];
__device__ float g_pS[NCHUNK * D_INNER * 16];
__device__ float g_hin[NCHUNK * D_INNER * 16];

// ---------------- WMMA fp16 GEMM (2 CTAs/SM, fused per-warp epilogue) -------
// C[M,N] = A'[M,Kp] @ B'[Kp,N] (+ bias / softplus unless split-K raw mode).
// 128x128 CTA tile, 8 warps of 32x64, K chunk = 64, static smem, no reg
// prefetch (occupancy covers latency; lesson from R14).
// Dual bias: col < biasSplit -> bias[col], else bias2[col - biasSplit].
// gridDim.z > 1 => split-K raw partials at C + z*(gridDim.y*128)*ldc.
__global__ __launch_bounds__(256, 2)
void wgemm(const half* __restrict__ A, const half* __restrict__ B,
           const float* __restrict__ bias, const float* __restrict__ bias2,
           int biasSplit, float* __restrict__ C,
           int Kp, int lda, int ldb, int ldc, int Nvalid, int softplus_ep)
{
    __shared__ half As[128][72];    // 64 cols + 8 pad
    __shared__ half Bs[64][136];    // 128 cols + 8 pad
    __shared__ float esc[8][256];   // per-warp 16x16 f32 epilogue scratch

    const int tid = threadIdx.x;
    const int wid = tid >> 5;
    const int lane = tid & 31;
    const int m0 = blockIdx.y * 128;
    const int n0 = blockIdx.x * 128;
    const int warp_m = (wid & 3) * 32;
    const int warp_n = (wid >> 2) * 64;

    const bool raw = (gridDim.z > 1);
    A += (size_t)blockIdx.z * Kp;
    B += (size_t)blockIdx.z * Kp * ldb;
    if (raw) C += (size_t)blockIdx.z * gridDim.y * 128 * ldc;

    wmma::fragment<wmma::accumulator, 16, 16, 16, float> acc[2][4];
    #pragma unroll
    for (int mi = 0; mi < 2; mi++)
        #pragma unroll
        for (int nj = 0; nj < 4; nj++)
            wmma::fill_fragment(acc[mi][nj], 0.f);

    for (int k0 = 0; k0 < Kp; k0 += 64) {
        // direct global -> smem tile copy (short register liveness)
        #pragma unroll
        for (int i = 0; i < 4; i++) {
            int idx = i * 256 + tid;
            int r = idx >> 3, c8 = (idx & 7) * 8;
            *(float4*)&As[r][c8] =
                *(const float4*)(A + (size_t)(m0 + r) * lda + k0 + c8);
        }
        #pragma unroll
        for (int i = 0; i < 4; i++) {
            int idx = i * 256 + tid;
            int r = idx >> 4, c8 = (idx & 15) * 8;
            *(float4*)&Bs[r][c8] =
                *(const float4*)(B + (size_t)(k0 + r) * ldb + n0 + c8);
        }
        __syncthreads();

        #pragma unroll
        for (int kk = 0; kk < 4; kk++) {
            wmma::fragment<wmma::matrix_a, 16, 16, 16, half, wmma::row_major> fa[2];
            wmma::fragment<wmma::matrix_b, 16, 16, 16, half, wmma::row_major> fb[4];
            #pragma unroll
            for (int mi = 0; mi < 2; mi++)
                wmma::load_matrix_sync(fa[mi], &As[warp_m + mi * 16][kk * 16], 72);
            #pragma unroll
            for (int nj = 0; nj < 4; nj++)
                wmma::load_matrix_sync(fb[nj], &Bs[kk * 16][warp_n + nj * 16], 136);
            #pragma unroll
            for (int mi = 0; mi < 2; mi++)
                #pragma unroll
                for (int nj = 0; nj < 4; nj++)
                    wmma::mma_sync(acc[mi][nj], fa[mi], fb[nj], acc[mi][nj]);
        }
        __syncthreads();
    }

    // fused epilogue: per-warp fragment roundtrip through esc (no block sync)
    #pragma unroll
    for (int mi = 0; mi < 2; mi++) {
        #pragma unroll
        for (int nj = 0; nj < 4; nj++) {
            int colf = n0 + warp_n + nj * 16;
            if (colf >= Nvalid) continue;
            wmma::store_matrix_sync(esc[wid], acc[mi][nj], 16, wmma::mem_row_major);
            __syncwarp();
            int r   = lane >> 1;
            int cb  = (lane & 1) * 8;
            int row = m0 + warp_m + mi * 16 + r;
            int col = colf + cb;
            float4 v0 = *(float4*)&esc[wid][r * 16 + cb];
            float4 v1 = *(float4*)&esc[wid][r * 16 + cb + 4];
            if (!raw) {
                const float* bp = (col >= biasSplit) ? (bias2 - biasSplit) : bias;
                v0.x += bp[col];     v0.y += bp[col + 1];
                v0.z += bp[col + 2]; v0.w += bp[col + 3];
                v1.x += bp[col + 4]; v1.y += bp[col + 5];
                v1.z += bp[col + 6]; v1.w += bp[col + 7];
                if (softplus_ep) {
                    v0.x = (v0.x > 20.f) ? v0.x : log1pf(expf(v0.x));
                    v0.y = (v0.y > 20.f) ? v0.y : log1pf(expf(v0.y));
                    v0.z = (v0.z > 20.f) ? v0.z : log1pf(expf(v0.z));
                    v0.w = (v0.w > 20.f) ? v0.w : log1pf(expf(v0.w));
                    v1.x = (v1.x > 20.f) ? v1.x : log1pf(expf(v1.x));
                    v1.y = (v1.y > 20.f) ? v1.y : log1pf(expf(v1.y));
                    v1.z = (v1.z > 20.f) ? v1.z : log1pf(expf(v1.z));
                    v1.w = (v1.w > 20.f) ? v1.w : log1pf(expf(v1.w));
                }
            }
            *(float4*)(C + (size_t)row * ldc + col)     = v0;
            *(float4*)(C + (size_t)row * ldc + col + 4) = v1;
            __syncwarp();
        }
    }
}

// reduce split-K partials for t: t[i] = bias[i%64] + sum_z part[z][i]
__global__ __launch_bounds__(256)
void reduce_t(const float* __restrict__ part, const float* __restrict__ bias,
              float* __restrict__ T)
{
    int i = blockIdx.x * 256 + threadIdx.x;
    float s = bias[i & 63];
    #pragma unroll
    for (int z = 0; z < SPLITK; z++)
        s += part[(size_t)z * (L_SEQ * DT_RANK) + i];
    T[i] = s;
}

// ---------------- split kernels (intrinsics only) ----------------
__device__ __forceinline__ void split1(float v, half& h, half& l) {
    h = __float2half_rn(v);
    l = __float2half_rn(v - __half2float(h));
}

__global__ __launch_bounds__(256)
void split_act(const float4* __restrict__ V, half* __restrict__ O,
               int K4, int K, int total4)
{
    int i = blockIdx.x * 256 + threadIdx.x;
    if (i >= total4) return;
    int m = i / K4;
    int k = (i - m * K4) * 4;
    float4 v = V[i];
    half h0, l0, h1, l1, h2, l2, h3, l3;
    split1(v.x, h0, l0); split1(v.y, h1, l1);
    split1(v.z, h2, l2); split1(v.w, h3, l3);
    half2* p0 = (half2*)(O + (size_t)m * 2 * K + k);
    half2* p1 = (half2*)(O + (size_t)m * 2 * K + K + k);
    p0[0] = half2{h0, h1}; p0[1] = half2{h2, h3};
    p1[0] = half2{l0, l1}; p1[1] = half2{l2, l3};
}

__global__ __launch_bounds__(256)
void split_w(const float4* __restrict__ W, half* __restrict__ O,
             int N4, int N, int ldb, int K, int total4)
{
    int i = blockIdx.x * 256 + threadIdx.x;
    if (i >= total4) return;
    int k = i / N4;
    int n = (i - k * N4) * 4;
    float4 v = W[i];
    half2 h01 = {__float2half_rn(v.x), __float2half_rn(v.y)};
    half2 h23 = {__float2half_rn(v.z), __float2half_rn(v.w)};
    half2* p0 = (half2*)(O + (size_t)k * ldb + n);
    half2* p1 = (half2*)(O + (size_t)(K + k) * ldb + n);
    p0[0] = h01; p0[1] = h23;
    p1[0] = h01; p1[1] = h23;
}

__global__ __launch_bounds__(256)
void pad_dt1(half* __restrict__ O)
{
    int i = blockIdx.x * 256 + threadIdx.x;
    int row = i >> 5;
    int c2  = (i & 31) * 2;
    ((half2*)(O + (size_t)row * 128 + 64 + c2))[0] = half2{(half)0.f, (half)0.f};
}

// ---------------- conv(width4) + SiLU + fp16 split (fused) ----------------
// U0 rows have stride 4096 (combined [u0|gate] buffer, u0 in cols 0..2047)
__global__ __launch_bounds__(256)
void conv_silu_split(const float* __restrict__ U0, const float* __restrict__ cw,
                     const float* __restrict__ cb, float* __restrict__ U,
                     half* __restrict__ UA)
{
    int idx = blockIdx.x * blockDim.x + threadIdx.x;
    if (idx >= L_SEQ * D_INNER) return;
    int d = idx & (D_INNER - 1);
    int l = idx >> 11;
    size_t src = (size_t)l * (2 * D_INNER) + d;
    float w0 = cw[d * 4 + 0], w1 = cw[d * 4 + 1], w2 = cw[d * 4 + 2], w3 = cw[d * 4 + 3];
    float acc = cb[d] + w3 * U0[src];
    if (l >= 1) acc = fmaf(w2, U0[src - 2 * D_INNER], acc);
    if (l >= 2) acc = fmaf(w1, U0[src - 4 * D_INNER], acc);
    if (l >= 3) acc = fmaf(w0, U0[src - 6 * D_INNER], acc);
    float s = acc / (1.f + expf(-acc));
    U[idx] = s;
    half h, lo;
    split1(s, h, lo);
    size_t base = (size_t)l * 2 * D_INNER + d;
    UA[base] = h;
    UA[base + D_INNER] = lo;
}

// ---------------- chunked 2-pass SSM scan ----------------
__global__ __launch_bounds__(256)
void scan_pass1(const float* __restrict__ delta, const float* __restrict__ u,
                const float* __restrict__ A_log, const float* __restrict__ Bm,
                float* __restrict__ hS, float* __restrict__ pS)
{
    const int tid  = threadIdx.x;
    const int n    = tid & 15;
    const int dgrp = tid >> 4;
    const int bx   = blockIdx.x;
    const int d     = (bx & 127) * 16 + dgrp;
    const int chunk = bx >> 7;

    const float A  = -expf(A_log[n]);
    const float Bn = Bm[n * D_INNER + d];
    const bool  smallA = fabsf(A) < 1e-6f;
    const float invA   = smallA ? 0.f : 1.f / A;

    float h = 0.f, p = 1.f;
    size_t idx = (size_t)(chunk * CHUNK) * D_INNER + d;
    for (int l = 0; l < CHUNK; l++) {
        float dt = delta[idx];
        float uu = u[idx];
        float dA = dt * A;
        float ab = __expf(dA);
        float ex = smallA ? dt * (1.f + 0.5f * dA) : (ab - 1.f) * invA;
        h = fmaf(ab, h, ex * Bn * uu);
        p *= ab;
        idx += D_INNER;
    }
    int o = (chunk * D_INNER + d) * 16 + n;
    hS[o] = h;
    pS[o] = p;
}

__global__ __launch_bounds__(256)
void scan_mid(const float* __restrict__ hS, const float* __restrict__ pS,
              float* __restrict__ hin)
{
    int i = blockIdx.x * 256 + threadIdx.x;
    int d = i >> 4, n = i & 15;
    float carry = 0.f;
    #pragma unroll
    for (int c = 0; c < NCHUNK; c++) {
        int o = (c * D_INNER + d) * 16 + n;
        hin[o] = carry;
        carry = fmaf(pS[o], carry, hS[o]);
    }
}

// gate is read from the combined buffer: row stride 4096, cols 2048..4095
__global__ __launch_bounds__(256)
void scan_pass2(const float* __restrict__ delta, const float* __restrict__ u,
                const float* __restrict__ ug, const float* __restrict__ A_log,
                const float* __restrict__ Bm, const float* __restrict__ Cm,
                const float* __restrict__ Dv, const float* __restrict__ hin,
                half* __restrict__ YA)
{
    const int tid  = threadIdx.x;
    const int n    = tid & 15;
    const int dgrp = tid >> 4;
    const int bx   = blockIdx.x;
    const int d     = (bx & 127) * 16 + dgrp;
    const int chunk = bx >> 7;

    const float A  = -expf(A_log[n]);
    const float Bn = Bm[n * D_INNER + d];
    const float Cn = Cm[n * D_INNER + d];
    const float Dd = Dv[d];
    const bool  smallA = fabsf(A) < 1e-6f;
    const float invA   = smallA ? 0.f : 1.f / A;

    float h = hin[(chunk * D_INNER + d) * 16 + n];
    size_t idx = (size_t)(chunk * CHUNK) * D_INNER + d;
    size_t gidx = (size_t)(chunk * CHUNK) * (2 * D_INNER) + D_INNER + d;
    size_t ybase = (size_t)(chunk * CHUNK) * 2 * D_INNER + d;
    for (int l = 0; l < CHUNK; l++) {
        float dt = delta[idx];
        float uu = u[idx];
        float dA = dt * A;
        float ab = __expf(dA);
        float ex = smallA ? dt * (1.f + 0.5f * dA) : (ab - 1.f) * invA;
        h = fmaf(ab, h, ex * Bn * uu);
        float c = h * Cn;
        c += __shfl_xor_sync(0xffffffffu, c, 1);
        c += __shfl_xor_sync(0xffffffffu, c, 2);
        c += __shfl_xor_sync(0xffffffffu, c, 4);
        c += __shfl_xor_sync(0xffffffffu, c, 8);
        if (n == 0) {
            float gg = ug[gidx];
            float sil = gg / (1.f + expf(-gg));
            float val = (c + Dd * uu) * sil;
            half hh, ll;
            split1(val, hh, ll);
            YA[ybase] = hh;
            YA[ybase + D_INNER] = ll;
        }
        idx += D_INNER;
        gidx += 2 * D_INNER;
        ybase += 2 * D_INNER;
    }
}

// ---------------- launcher ----------------
extern "C" void kernel_launch(void* const* d_in, const int* in_sizes, int n_in,
                              void* d_out, int out_size)
{
    const float* x      = (const float*)d_in[0];
    const float* in_w   = (const float*)d_in[1];
    const float* in_b   = (const float*)d_in[2];
    const float* conv_w = (const float*)d_in[3];
    const float* conv_b = (const float*)d_in[4];
    const float* A_log  = (const float*)d_in[5];
    const float* B_mat  = (const float*)d_in[6];
    const float* C_mat  = (const float*)d_in[7];
    const float* D_vec  = (const float*)d_in[8];
    const float* gate_w = (const float*)d_in[9];
    const float* gate_b = (const float*)d_in[10];
    const float* dt1_w  = (const float*)d_in[11];
    const float* dt1_b  = (const float*)d_in[12];
    const float* dt2_w  = (const float*)d_in[13];
    const float* dt2_b  = (const float*)d_in[14];
    const float* out_w  = (const float*)d_in[15];
    const float* out_b  = (const float*)d_in[16];
    float* out = (float*)d_out;

    float *ug, *u, *t, *tpart, *delta, *hS, *pS, *hin;
    half *xA, *uA, *tA, *yA, *ugB, *dt1B, *dt2B, *outB;
    cudaGetSymbolAddress((void**)&ug, g_ug);       cudaGetSymbolAddress((void**)&u, g_u);
    cudaGetSymbolAddress((void**)&t, g_t);         cudaGetSymbolAddress((void**)&tpart, g_tpart);
    cudaGetSymbolAddress((void**)&delta, g_delta);
    cudaGetSymbolAddress((void**)&hS, g_hS);       cudaGetSymbolAddress((void**)&pS, g_pS);
    cudaGetSymbolAddress((void**)&hin, g_hin);
    cudaGetSymbolAddress((void**)&xA, g_xA);       cudaGetSymbolAddress((void**)&uA, g_uA);
    cudaGetSymbolAddress((void**)&tA, g_tA);       cudaGetSymbolAddress((void**)&yA, g_yA);
    cudaGetSymbolAddress((void**)&ugB, g_ugB);
    cudaGetSymbolAddress((void**)&dt1B, g_dt1B);   cudaGetSymbolAddress((void**)&dt2B, g_dt2B);
    cudaGetSymbolAddress((void**)&outB, g_outB);

    // 1) in-proj weights -> combined buffer cols [0,2048)
    split_w<<<(D_MODEL * D_INNER / 4 + 255) / 256, 256>>>((const float4*)in_w, ugB,
        D_INNER / 4, D_INNER, 2 * D_INNER, D_MODEL, D_MODEL * D_INNER / 4);
    // 2) gate weights -> combined buffer cols [2048,4096)
    split_w<<<(D_MODEL * D_INNER / 4 + 255) / 256, 256>>>((const float4*)gate_w,
        ugB + D_INNER, D_INNER / 4, D_INNER, 2 * D_INNER, D_MODEL,
        D_MODEL * D_INNER / 4);
    // 3) x split
    split_act<<<(L_SEQ * D_MODEL / 4 + 255) / 256, 256>>>((const float4*)x, xA,
        D_MODEL / 4, D_MODEL, L_SEQ * D_MODEL / 4);
    // 4) fused in+gate GEMM (N=4096)  <-- profiled slot
    wgemm<<<dim3((2 * D_INNER) / 128, L_SEQ / 128, 1), 256>>>(
        xA, ugB, in_b, gate_b, D_INNER, ug,
        2 * D_MODEL, 2 * D_MODEL, 2 * D_INNER, 2 * D_INNER, 2 * D_INNER, 0);

    // remaining weight prep
    split_w<<<(D_INNER * DT_RANK / 4 + 255) / 256, 256>>>((const float4*)dt1_w, dt1B,
        DT_RANK / 4, DT_RANK, 128, D_INNER, D_INNER * DT_RANK / 4);
    pad_dt1<<<(2 * D_INNER * 32 + 255) / 256, 256>>>(dt1B);
    split_w<<<(DT_RANK * D_INNER / 4 + 255) / 256, 256>>>((const float4*)dt2_w, dt2B,
        D_INNER / 4, D_INNER, D_INNER, DT_RANK, DT_RANK * D_INNER / 4);
    split_w<<<(D_INNER * D_MODEL / 4 + 255) / 256, 256>>>((const float4*)out_w, outB,
        D_MODEL / 4, D_MODEL, D_MODEL, D_INNER, D_INNER * D_MODEL / 4);

    // conv + silu + split (reads u0 from combined buffer, stride 4096)
    conv_silu_split<<<(L_SEQ * D_INNER) / 256, 256>>>(ug, conv_w, conv_b, u, uA);

    // dt1: split-K=8 raw partials + reduce
    wgemm<<<dim3(1, L_SEQ / 128, SPLITK), 256>>>(
        uA, dt1B, dt1_b, dt1_b, 1 << 30, tpart,
        (2 * D_INNER) / SPLITK, 2 * D_INNER, 128, DT_RANK, DT_RANK, 0);
    reduce_t<<<(L_SEQ * DT_RANK) / 256, 256>>>(tpart, dt1_b, t);

    // t split + dt2 (+softplus)
    split_act<<<(L_SEQ * DT_RANK / 4 + 255) / 256, 256>>>((const float4*)t, tA,
        DT_RANK / 4, DT_RANK, L_SEQ * DT_RANK / 4);
    wgemm<<<dim3(D_INNER / 128, L_SEQ / 128, 1), 256>>>(
        tA, dt2B, dt2_b, dt2_b, 1 << 30, delta,
        2 * DT_RANK, 2 * DT_RANK, D_INNER, D_INNER, D_INNER, 1);

    // chunked scan (pass2 reads gate from combined buffer, emits fp16 split y)
    scan_pass1<<<NCHUNK * (D_INNER / 16), 256>>>(delta, u, A_log, B_mat, hS, pS);
    scan_mid<<<(D_INNER * 16) / 256, 256>>>(hS, pS, hin);
    scan_pass2<<<NCHUNK * (D_INNER / 16), 256>>>(delta, u, ug, A_log, B_mat,
                                                 C_mat, D_vec, hin, yA);

    // out-proj
    wgemm<<<dim3(D_MODEL / 128, L_SEQ / 128, 1), 256>>>(
        yA, outB, out_b, out_b, 1 << 30, out,
        2 * D_INNER, 2 * D_INNER, D_MODEL, D_MODEL, D_MODEL, 0);
}

// round 17
// speedup vs baseline: 1.8734x; 1.0631x over previous
#include <cuda_runtime.h>
#include <cuda_fp16.h>
#include <cuda_pipeline.h>
#include <mma.h>
#include <math.h>

using namespace nvcuda;

// ---------------- problem constants ----------------
#define L_SEQ   2048
#define D_MODEL 1024
#define D_INNER 2048
#define DT_RANK 64
#define NCHUNK  16
#define CHUNK   128
#define SPLITK  8

// ---------------- scratch (no allocations allowed) ----------------
__device__ float g_ug[L_SEQ * 2 * D_INNER];     // [u0 | gate] combined, ld 4096
__device__ float g_u[L_SEQ * D_INNER];
__device__ float g_t[L_SEQ * DT_RANK];
__device__ float g_tpart[SPLITK * L_SEQ * DT_RANK];
__device__ float g_delta[L_SEQ * D_INNER];

// split fp16 activations A' = [Ah | Al]  (M x 2K)
__device__ half g_xA[L_SEQ * 2 * D_MODEL];
__device__ half g_uA[L_SEQ * 2 * D_INNER];
__device__ half g_tA[L_SEQ * 2 * DT_RANK];
__device__ half g_yA[L_SEQ * 2 * D_INNER];

// fp16 weights B' = [Bh ; Bh]  (2K x ldb)
__device__ half g_ugB[2 * D_MODEL * 2 * D_INNER];   // [in | gate] fused, ldb 4096
__device__ half g_dt1B[2 * D_INNER * 128];          // N padded 64 -> 128
__device__ half g_dt2B[2 * DT_RANK * D_INNER];
__device__ half g_outB[2 * D_INNER * D_MODEL];

// chunked scan state
__device__ float g_hS[NCHUNK * D_INNER * 16];
__device__ float g_pS[NCHUNK * D_INNER * 16];
__device__ float g_hin[NCHUNK * D_INNER * 16];

// ---------------- WMMA fp16 GEMM (cp.async 2-stage, fused epilogue) ---------
// C[M,N] = A'[M,Kp] @ B'[Kp,N] (+ bias / softplus unless split-K raw mode).
// 128x128 CTA tile, 8 warps of 32x64, K chunk = 64.
// Tile loads via __pipeline_memcpy_async (LDGSTS) into 2-stage dynamic smem;
// epilogue scratch aliased into stage 0 after the final sync.
#define A_STAGE_B 18432                    // 128*72 halves
#define B_STAGE_B 17408                    // 64*136 halves
#define STAGE_B   (A_STAGE_B + B_STAGE_B)  // 35840
#define WG_SMEM   (2 * STAGE_B)            // 71680

__global__ __launch_bounds__(256, 2)
void wgemm(const half* __restrict__ A, const half* __restrict__ B,
           const float* __restrict__ bias, const float* __restrict__ bias2,
           int biasSplit, float* __restrict__ C,
           int Kp, int lda, int ldb, int ldc, int Nvalid, int softplus_ep)
{
    extern __shared__ unsigned char dynsmem[];

    const int tid = threadIdx.x;
    const int wid = tid >> 5;
    const int lane = tid & 31;
    const int m0 = blockIdx.y * 128;
    const int n0 = blockIdx.x * 128;
    const int warp_m = (wid & 3) * 32;
    const int warp_n = (wid >> 2) * 64;

    const bool raw = (gridDim.z > 1);
    A += (size_t)blockIdx.z * Kp;
    B += (size_t)blockIdx.z * Kp * ldb;
    if (raw) C += (size_t)blockIdx.z * gridDim.y * 128 * ldc;

    wmma::fragment<wmma::accumulator, 16, 16, 16, float> acc[2][4];
    #pragma unroll
    for (int mi = 0; mi < 2; mi++)
        #pragma unroll
        for (int nj = 0; nj < 4; nj++)
            wmma::fill_fragment(acc[mi][nj], 0.f);

    auto load_stage = [&](int c, int s) {
        half* as = (half*)(dynsmem + (size_t)s * STAGE_B);
        half* bs = (half*)(dynsmem + (size_t)s * STAGE_B + A_STAGE_B);
        int k0 = c << 6;
        #pragma unroll
        for (int i = 0; i < 4; i++) {
            int idx = i * 256 + tid;
            int r = idx >> 3, c8 = (idx & 7) * 8;
            __pipeline_memcpy_async(as + r * 72 + c8,
                A + (size_t)(m0 + r) * lda + k0 + c8, 16);
        }
        #pragma unroll
        for (int i = 0; i < 4; i++) {
            int idx = i * 256 + tid;
            int r = idx >> 4, c8 = (idx & 15) * 8;
            __pipeline_memcpy_async(bs + r * 136 + c8,
                B + (size_t)(k0 + r) * ldb + n0 + c8, 16);
        }
        __pipeline_commit();
    };

    const int nc = Kp >> 6;
    load_stage(0, 0);

    for (int c = 0; c < nc; c++) {
        if (c + 1 < nc) {
            load_stage(c + 1, (c + 1) & 1);
            __pipeline_wait_prior(1);
        } else {
            __pipeline_wait_prior(0);
        }
        __syncthreads();

        const half* as = (const half*)(dynsmem + (size_t)(c & 1) * STAGE_B);
        const half* bs = (const half*)(dynsmem + (size_t)(c & 1) * STAGE_B + A_STAGE_B);
        #pragma unroll
        for (int kk = 0; kk < 4; kk++) {
            wmma::fragment<wmma::matrix_a, 16, 16, 16, half, wmma::row_major> fa[2];
            wmma::fragment<wmma::matrix_b, 16, 16, 16, half, wmma::row_major> fb[4];
            #pragma unroll
            for (int mi = 0; mi < 2; mi++)
                wmma::load_matrix_sync(fa[mi], as + (warp_m + mi * 16) * 72 + kk * 16, 72);
            #pragma unroll
            for (int nj = 0; nj < 4; nj++)
                wmma::load_matrix_sync(fb[nj], bs + (kk * 16) * 136 + warp_n + nj * 16, 136);
            #pragma unroll
            for (int mi = 0; mi < 2; mi++)
                #pragma unroll
                for (int nj = 0; nj < 4; nj++)
                    wmma::mma_sync(acc[mi][nj], fa[mi], fb[nj], acc[mi][nj]);
        }
        __syncthreads();
    }

    // fused epilogue: per-warp scratch aliased into stage memory (safe after
    // the final __syncthreads above — no tile reads remain)
    float* esc = (float*)dynsmem + wid * 256;
    #pragma unroll
    for (int mi = 0; mi < 2; mi++) {
        #pragma unroll
        for (int nj = 0; nj < 4; nj++) {
            int colf = n0 + warp_n + nj * 16;
            if (colf >= Nvalid) continue;
            wmma::store_matrix_sync(esc, acc[mi][nj], 16, wmma::mem_row_major);
            __syncwarp();
            int r   = lane >> 1;
            int cb  = (lane & 1) * 8;
            int row = m0 + warp_m + mi * 16 + r;
            int col = colf + cb;
            float4 v0 = *(float4*)&esc[r * 16 + cb];
            float4 v1 = *(float4*)&esc[r * 16 + cb + 4];
            if (!raw) {
                const float* bp = (col >= biasSplit) ? (bias2 - biasSplit) : bias;
                v0.x += bp[col];     v0.y += bp[col + 1];
                v0.z += bp[col + 2]; v0.w += bp[col + 3];
                v1.x += bp[col + 4]; v1.y += bp[col + 5];
                v1.z += bp[col + 6]; v1.w += bp[col + 7];
                if (softplus_ep) {
                    v0.x = (v0.x > 20.f) ? v0.x : log1pf(expf(v0.x));
                    v0.y = (v0.y > 20.f) ? v0.y : log1pf(expf(v0.y));
                    v0.z = (v0.z > 20.f) ? v0.z : log1pf(expf(v0.z));
                    v0.w = (v0.w > 20.f) ? v0.w : log1pf(expf(v0.w));
                    v1.x = (v1.x > 20.f) ? v1.x : log1pf(expf(v1.x));
                    v1.y = (v1.y > 20.f) ? v1.y : log1pf(expf(v1.y));
                    v1.z = (v1.z > 20.f) ? v1.z : log1pf(expf(v1.z));
                    v1.w = (v1.w > 20.f) ? v1.w : log1pf(expf(v1.w));
                }
            }
            *(float4*)(C + (size_t)row * ldc + col)     = v0;
            *(float4*)(C + (size_t)row * ldc + col + 4) = v1;
            __syncwarp();
        }
    }
}

// reduce split-K partials for t: t[i] = bias[i%64] + sum_z part[z][i]
__global__ __launch_bounds__(256)
void reduce_t(const float* __restrict__ part, const float* __restrict__ bias,
              float* __restrict__ T)
{
    int i = blockIdx.x * 256 + threadIdx.x;
    float s = bias[i & 63];
    #pragma unroll
    for (int z = 0; z < SPLITK; z++)
        s += part[(size_t)z * (L_SEQ * DT_RANK) + i];
    T[i] = s;
}

// ---------------- split kernels (intrinsics only) ----------------
__device__ __forceinline__ void split1(float v, half& h, half& l) {
    h = __float2half_rn(v);
    l = __float2half_rn(v - __half2float(h));
}

__global__ __launch_bounds__(256)
void split_act(const float4* __restrict__ V, half* __restrict__ O,
               int K4, int K, int total4)
{
    int i = blockIdx.x * 256 + threadIdx.x;
    if (i >= total4) return;
    int m = i / K4;
    int k = (i - m * K4) * 4;
    float4 v = V[i];
    half h0, l0, h1, l1, h2, l2, h3, l3;
    split1(v.x, h0, l0); split1(v.y, h1, l1);
    split1(v.z, h2, l2); split1(v.w, h3, l3);
    half2* p0 = (half2*)(O + (size_t)m * 2 * K + k);
    half2* p1 = (half2*)(O + (size_t)m * 2 * K + K + k);
    p0[0] = half2{h0, h1}; p0[1] = half2{h2, h3};
    p1[0] = half2{l0, l1}; p1[1] = half2{l2, l3};
}

__global__ __launch_bounds__(256)
void split_w(const float4* __restrict__ W, half* __restrict__ O,
             int N4, int N, int ldb, int K, int total4)
{
    int i = blockIdx.x * 256 + threadIdx.x;
    if (i >= total4) return;
    int k = i / N4;
    int n = (i - k * N4) * 4;
    float4 v = W[i];
    half2 h01 = {__float2half_rn(v.x), __float2half_rn(v.y)};
    half2 h23 = {__float2half_rn(v.z), __float2half_rn(v.w)};
    half2* p0 = (half2*)(O + (size_t)k * ldb + n);
    half2* p1 = (half2*)(O + (size_t)(K + k) * ldb + n);
    p0[0] = h01; p0[1] = h23;
    p1[0] = h01; p1[1] = h23;
}

__global__ __launch_bounds__(256)
void pad_dt1(half* __restrict__ O)
{
    int i = blockIdx.x * 256 + threadIdx.x;
    int row = i >> 5;
    int c2  = (i & 31) * 2;
    ((half2*)(O + (size_t)row * 128 + 64 + c2))[0] = half2{(half)0.f, (half)0.f};
}

// ---------------- conv(width4) + SiLU + fp16 split (fused) ----------------
// U0 rows have stride 4096 (combined [u0|gate] buffer, u0 in cols 0..2047)
__global__ __launch_bounds__(256)
void conv_silu_split(const float* __restrict__ U0, const float* __restrict__ cw,
                     const float* __restrict__ cb, float* __restrict__ U,
                     half* __restrict__ UA)
{
    int idx = blockIdx.x * blockDim.x + threadIdx.x;
    if (idx >= L_SEQ * D_INNER) return;
    int d = idx & (D_INNER - 1);
    int l = idx >> 11;
    size_t src = (size_t)l * (2 * D_INNER) + d;
    float w0 = cw[d * 4 + 0], w1 = cw[d * 4 + 1], w2 = cw[d * 4 + 2], w3 = cw[d * 4 + 3];
    float acc = cb[d] + w3 * U0[src];
    if (l >= 1) acc = fmaf(w2, U0[src - 2 * D_INNER], acc);
    if (l >= 2) acc = fmaf(w1, U0[src - 4 * D_INNER], acc);
    if (l >= 3) acc = fmaf(w0, U0[src - 6 * D_INNER], acc);
    float s = acc / (1.f + expf(-acc));
    U[idx] = s;
    half h, lo;
    split1(s, h, lo);
    size_t base = (size_t)l * 2 * D_INNER + d;
    UA[base] = h;
    UA[base + D_INNER] = lo;
}

// ---------------- chunked 2-pass SSM scan ----------------
__global__ __launch_bounds__(256)
void scan_pass1(const float* __restrict__ delta, const float* __restrict__ u,
                const float* __restrict__ A_log, const float* __restrict__ Bm,
                float* __restrict__ hS, float* __restrict__ pS)
{
    const int tid  = threadIdx.x;
    const int n    = tid & 15;
    const int dgrp = tid >> 4;
    const int bx   = blockIdx.x;
    const int d     = (bx & 127) * 16 + dgrp;
    const int chunk = bx >> 7;

    const float A  = -expf(A_log[n]);
    const float Bn = Bm[n * D_INNER + d];
    const bool  smallA = fabsf(A) < 1e-6f;
    const float invA   = smallA ? 0.f : 1.f / A;

    float h = 0.f, p = 1.f;
    size_t idx = (size_t)(chunk * CHUNK) * D_INNER + d;
    for (int l = 0; l < CHUNK; l++) {
        float dt = delta[idx];
        float uu = u[idx];
        float dA = dt * A;
        float ab = __expf(dA);
        float ex = smallA ? dt * (1.f + 0.5f * dA) : (ab - 1.f) * invA;
        h = fmaf(ab, h, ex * Bn * uu);
        p *= ab;
        idx += D_INNER;
    }
    int o = (chunk * D_INNER + d) * 16 + n;
    hS[o] = h;
    pS[o] = p;
}

__global__ __launch_bounds__(256)
void scan_mid(const float* __restrict__ hS, const float* __restrict__ pS,
              float* __restrict__ hin)
{
    int i = blockIdx.x * 256 + threadIdx.x;
    int d = i >> 4, n = i & 15;
    float carry = 0.f;
    #pragma unroll
    for (int c = 0; c < NCHUNK; c++) {
        int o = (c * D_INNER + d) * 16 + n;
        hin[o] = carry;
        carry = fmaf(pS[o], carry, hS[o]);
    }
}

// gate is read from the combined buffer: row stride 4096, cols 2048..4095
__global__ __launch_bounds__(256)
void scan_pass2(const float* __restrict__ delta, const float* __restrict__ u,
                const float* __restrict__ ug, const float* __restrict__ A_log,
                const float* __restrict__ Bm, const float* __restrict__ Cm,
                const float* __restrict__ Dv, const float* __restrict__ hin,
                half* __restrict__ YA)
{
    const int tid  = threadIdx.x;
    const int n    = tid & 15;
    const int dgrp = tid >> 4;
    const int bx   = blockIdx.x;
    const int d     = (bx & 127) * 16 + dgrp;
    const int chunk = bx >> 7;

    const float A  = -expf(A_log[n]);
    const float Bn = Bm[n * D_INNER + d];
    const float Cn = Cm[n * D_INNER + d];
    const float Dd = Dv[d];
    const bool  smallA = fabsf(A) < 1e-6f;
    const float invA   = smallA ? 0.f : 1.f / A;

    float h = hin[(chunk * D_INNER + d) * 16 + n];
    size_t idx = (size_t)(chunk * CHUNK) * D_INNER + d;
    size_t gidx = (size_t)(chunk * CHUNK) * (2 * D_INNER) + D_INNER + d;
    size_t ybase = (size_t)(chunk * CHUNK) * 2 * D_INNER + d;
    for (int l = 0; l < CHUNK; l++) {
        float dt = delta[idx];
        float uu = u[idx];
        float dA = dt * A;
        float ab = __expf(dA);
        float ex = smallA ? dt * (1.f + 0.5f * dA) : (ab - 1.f) * invA;
        h = fmaf(ab, h, ex * Bn * uu);
        float c = h * Cn;
        c += __shfl_xor_sync(0xffffffffu, c, 1);
        c += __shfl_xor_sync(0xffffffffu, c, 2);
        c += __shfl_xor_sync(0xffffffffu, c, 4);
        c += __shfl_xor_sync(0xffffffffu, c, 8);
        if (n == 0) {
            float gg = ug[gidx];
            float sil = gg / (1.f + expf(-gg));
            float val = (c + Dd * uu) * sil;
            half hh, ll;
            split1(val, hh, ll);
            YA[ybase] = hh;
            YA[ybase + D_INNER] = ll;
        }
        idx += D_INNER;
        gidx += 2 * D_INNER;
        ybase += 2 * D_INNER;
    }
}

// ---------------- launcher ----------------
extern "C" void kernel_launch(void* const* d_in, const int* in_sizes, int n_in,
                              void* d_out, int out_size)
{
    const float* x      = (const float*)d_in[0];
    const float* in_w   = (const float*)d_in[1];
    const float* in_b   = (const float*)d_in[2];
    const float* conv_w = (const float*)d_in[3];
    const float* conv_b = (const float*)d_in[4];
    const float* A_log  = (const float*)d_in[5];
    const float* B_mat  = (const float*)d_in[6];
    const float* C_mat  = (const float*)d_in[7];
    const float* D_vec  = (const float*)d_in[8];
    const float* gate_w = (const float*)d_in[9];
    const float* gate_b = (const float*)d_in[10];
    const float* dt1_w  = (const float*)d_in[11];
    const float* dt1_b  = (const float*)d_in[12];
    const float* dt2_w  = (const float*)d_in[13];
    const float* dt2_b  = (const float*)d_in[14];
    const float* out_w  = (const float*)d_in[15];
    const float* out_b  = (const float*)d_in[16];
    float* out = (float*)d_out;

    float *ug, *u, *t, *tpart, *delta, *hS, *pS, *hin;
    half *xA, *uA, *tA, *yA, *ugB, *dt1B, *dt2B, *outB;
    cudaGetSymbolAddress((void**)&ug, g_ug);       cudaGetSymbolAddress((void**)&u, g_u);
    cudaGetSymbolAddress((void**)&t, g_t);         cudaGetSymbolAddress((void**)&tpart, g_tpart);
    cudaGetSymbolAddress((void**)&delta, g_delta);
    cudaGetSymbolAddress((void**)&hS, g_hS);       cudaGetSymbolAddress((void**)&pS, g_pS);
    cudaGetSymbolAddress((void**)&hin, g_hin);
    cudaGetSymbolAddress((void**)&xA, g_xA);       cudaGetSymbolAddress((void**)&uA, g_uA);
    cudaGetSymbolAddress((void**)&tA, g_tA);       cudaGetSymbolAddress((void**)&yA, g_yA);
    cudaGetSymbolAddress((void**)&ugB, g_ugB);
    cudaGetSymbolAddress((void**)&dt1B, g_dt1B);   cudaGetSymbolAddress((void**)&dt2B, g_dt2B);
    cudaGetSymbolAddress((void**)&outB, g_outB);

    cudaFuncSetAttribute(wgemm, cudaFuncAttributeMaxDynamicSharedMemorySize, WG_SMEM);

    // 1) in-proj weights -> combined buffer cols [0,2048)
    split_w<<<(D_MODEL * D_INNER / 4 + 255) / 256, 256>>>((const float4*)in_w, ugB,
        D_INNER / 4, D_INNER, 2 * D_INNER, D_MODEL, D_MODEL * D_INNER / 4);
    // 2) gate weights -> combined buffer cols [2048,4096)
    split_w<<<(D_MODEL * D_INNER / 4 + 255) / 256, 256>>>((const float4*)gate_w,
        ugB + D_INNER, D_INNER / 4, D_INNER, 2 * D_INNER, D_MODEL,
        D_MODEL * D_INNER / 4);
    // 3) x split
    split_act<<<(L_SEQ * D_MODEL / 4 + 255) / 256, 256>>>((const float4*)x, xA,
        D_MODEL / 4, D_MODEL, L_SEQ * D_MODEL / 4);
    // 4) fused in+gate GEMM (N=4096)  <-- profiled slot
    wgemm<<<dim3((2 * D_INNER) / 128, L_SEQ / 128, 1), 256, WG_SMEM>>>(
        xA, ugB, in_b, gate_b, D_INNER, ug,
        2 * D_MODEL, 2 * D_MODEL, 2 * D_INNER, 2 * D_INNER, 2 * D_INNER, 0);

    // remaining weight prep
    split_w<<<(D_INNER * DT_RANK / 4 + 255) / 256, 256>>>((const float4*)dt1_w, dt1B,
        DT_RANK / 4, DT_RANK, 128, D_INNER, D_INNER * DT_RANK / 4);
    pad_dt1<<<(2 * D_INNER * 32 + 255) / 256, 256>>>(dt1B);
    split_w<<<(DT_RANK * D_INNER / 4 + 255) / 256, 256>>>((const float4*)dt2_w, dt2B,
        D_INNER / 4, D_INNER, D_INNER, DT_RANK, DT_RANK * D_INNER / 4);
    split_w<<<(D_INNER * D_MODEL / 4 + 255) / 256, 256>>>((const float4*)out_w, outB,
        D_MODEL / 4, D_MODEL, D_MODEL, D_INNER, D_INNER * D_MODEL / 4);

    // conv + silu + split (reads u0 from combined buffer, stride 4096)
    conv_silu_split<<<(L_SEQ * D_INNER) / 256, 256>>>(ug, conv_w, conv_b, u, uA);

    // dt1: split-K=8 raw partials + reduce
    wgemm<<<dim3(1, L_SEQ / 128, SPLITK), 256, WG_SMEM>>>(
        uA, dt1B, dt1_b, dt1_b, 1 << 30, tpart,
        (2 * D_INNER) / SPLITK, 2 * D_INNER, 128, DT_RANK, DT_RANK, 0);
    reduce_t<<<(L_SEQ * DT_RANK) / 256, 256>>>(tpart, dt1_b, t);

    // t split + dt2 (+softplus)
    split_act<<<(L_SEQ * DT_RANK / 4 + 255) / 256, 256>>>((const float4*)t, tA,
        DT_RANK / 4, DT_RANK, L_SEQ * DT_RANK / 4);
    wgemm<<<dim3(D_INNER / 128, L_SEQ / 128, 1), 256, WG_SMEM>>>(
        tA, dt2B, dt2_b, dt2_b, 1 << 30, delta,
        2 * DT_RANK, 2 * DT_RANK, D_INNER, D_INNER, D_INNER, 1);

    // chunked scan (pass2 reads gate from combined buffer, emits fp16 split y)
    scan_pass1<<<NCHUNK * (D_INNER / 16), 256>>>(delta, u, A_log, B_mat, hS, pS);
    scan_mid<<<(D_INNER * 16) / 256, 256>>>(hS, pS, hin);
    scan_pass2<<<NCHUNK * (D_INNER / 16), 256>>>(delta, u, ug, A_log, B_mat,
                                                 C_mat, D_vec, hin, yA);

    // out-proj
    wgemm<<<dim3(D_MODEL / 128, L_SEQ / 128, 1), 256, WG_SMEM>>>(
        yA, outB, out_b, out_b, 1 << 30, out,
        2 * D_INNER, 2 * D_INNER, D_MODEL, D_MODEL, D_MODEL, 0);
}